// round 2
// baseline (speedup 1.0000x reference)
#include <cuda_runtime.h>
#include <math.h>

// ---------------------------------------------------------------------------
// Complex helpers (float2 = {re, im})
// ---------------------------------------------------------------------------
__device__ __forceinline__ float2 cmul(float2 a, float2 b) {
    return make_float2(a.x * b.x - a.y * b.y, a.x * b.y + a.y * b.x);
}

// ---------------------------------------------------------------------------
// Kernel A: QCNN. The 8-qubit circuit factorizes over pairs (0,1)(2,3)(4,5)(6,7);
// Z_7 depends only on the (6,7) subsystem -> 4-amplitude simulation.
// Relevant params: w[9:12] (conv on (6,7)), w[21:24] (pool on (6,7)).
// State s[b6][b7]: s00,s01,s10,s11 (complex).
// ---------------------------------------------------------------------------
__global__ void qcnn_kernel(const float* __restrict__ x,
                            const float* __restrict__ w,
                            float* __restrict__ out) {
    int i = blockIdx.x * blockDim.x + threadIdx.x;
    if (i >= 2048) return;

    // Feature map per qubit: |psi> = P(phi) H P(phi) H |0>, phi = 2*x
    // a0 = (1+e^{i phi})/2 ; a1 = e^{i phi} (1-e^{i phi})/2
    float2 q6a0, q6a1, q7a0, q7a1;
    {
        float ph = 2.0f * x[i * 8 + 6];
        float sp, cp; sincosf(ph, &sp, &cp);
        q6a0 = make_float2(0.5f * (1.0f + cp), 0.5f * sp);
        float2 t = make_float2(0.5f * (1.0f - cp), -0.5f * sp);
        q6a1 = make_float2(cp * t.x - sp * t.y, cp * t.y + sp * t.x);
    }
    {
        float ph = 2.0f * x[i * 8 + 7];
        float sp, cp; sincosf(ph, &sp, &cp);
        q7a0 = make_float2(0.5f * (1.0f + cp), 0.5f * sp);
        float2 t = make_float2(0.5f * (1.0f - cp), -0.5f * sp);
        q7a1 = make_float2(cp * t.x - sp * t.y, cp * t.y + sp * t.x);
    }

    float2 s00 = cmul(q6a0, q7a0);
    float2 s01 = cmul(q6a0, q7a1);
    float2 s10 = cmul(q6a1, q7a0);
    float2 s11 = cmul(q6a1, q7a1);

    const float R = 0.70710678118654752f;
    const float2 ePp = make_float2(R,  R);   // e^{+i pi/4}
    const float2 ePm = make_float2(R, -R);   // e^{-i pi/4}

    float w9 = w[9], w10 = w[10], w11 = w[11];
    float w21 = w[21], w22 = w[22], w23 = w[23];

    // ---- conv_block(p = w[9:12], q1=6, q2=7) ----
    // 1) RZ(-pi/2) on q7: b7=0 *= e^{+i pi/4}, b7=1 *= e^{-i pi/4}
    s00 = cmul(s00, ePp); s10 = cmul(s10, ePp);
    s01 = cmul(s01, ePm); s11 = cmul(s11, ePm);
    // 2) CNOT c=7,t=6: where b7==1 flip b6 -> swap s01<->s11
    { float2 t = s01; s01 = s11; s11 = t; }
    // 3) RZ(w9) on q6
    {
        float hs, hc; sincosf(0.5f * w9, &hs, &hc);
        float2 em = make_float2(hc, -hs), ep = make_float2(hc, hs);
        s00 = cmul(s00, em); s01 = cmul(s01, em);
        s10 = cmul(s10, ep); s11 = cmul(s11, ep);
    }
    // 4) RY(w10) on q7
    {
        float hs, hc; sincosf(0.5f * w10, &hs, &hc);
        float2 u = s00, v = s01;
        s00 = make_float2(hc * u.x - hs * v.x, hc * u.y - hs * v.y);
        s01 = make_float2(hs * u.x + hc * v.x, hs * u.y + hc * v.y);
        u = s10; v = s11;
        s10 = make_float2(hc * u.x - hs * v.x, hc * u.y - hs * v.y);
        s11 = make_float2(hs * u.x + hc * v.x, hs * u.y + hc * v.y);
    }
    // 5) CNOT c=6,t=7: swap s10<->s11
    { float2 t = s10; s10 = s11; s11 = t; }
    // 6) RY(w11) on q7
    {
        float hs, hc; sincosf(0.5f * w11, &hs, &hc);
        float2 u = s00, v = s01;
        s00 = make_float2(hc * u.x - hs * v.x, hc * u.y - hs * v.y);
        s01 = make_float2(hs * u.x + hc * v.x, hs * u.y + hc * v.y);
        u = s10; v = s11;
        s10 = make_float2(hc * u.x - hs * v.x, hc * u.y - hs * v.y);
        s11 = make_float2(hs * u.x + hc * v.x, hs * u.y + hc * v.y);
    }
    // 7) CNOT c=7,t=6: swap s01<->s11
    { float2 t = s01; s01 = s11; s11 = t; }
    // 8) RZ(pi/2) on q6: b6=0 *= e^{-i pi/4}, b6=1 *= e^{+i pi/4}
    s00 = cmul(s00, ePm); s01 = cmul(s01, ePm);
    s10 = cmul(s10, ePp); s11 = cmul(s11, ePp);

    // ---- pool_block(p = w[21:24], src=6, sink=7) ----
    // 1) RZ(-pi/2) on q7
    s00 = cmul(s00, ePp); s10 = cmul(s10, ePp);
    s01 = cmul(s01, ePm); s11 = cmul(s11, ePm);
    // 2) CNOT c=7,t=6: swap s01<->s11
    { float2 t = s01; s01 = s11; s11 = t; }
    // 3) RZ(w21) on q6
    {
        float hs, hc; sincosf(0.5f * w21, &hs, &hc);
        float2 em = make_float2(hc, -hs), ep = make_float2(hc, hs);
        s00 = cmul(s00, em); s01 = cmul(s01, em);
        s10 = cmul(s10, ep); s11 = cmul(s11, ep);
    }
    // 4) RY(w22) on q7
    {
        float hs, hc; sincosf(0.5f * w22, &hs, &hc);
        float2 u = s00, v = s01;
        s00 = make_float2(hc * u.x - hs * v.x, hc * u.y - hs * v.y);
        s01 = make_float2(hs * u.x + hc * v.x, hs * u.y + hc * v.y);
        u = s10; v = s11;
        s10 = make_float2(hc * u.x - hs * v.x, hc * u.y - hs * v.y);
        s11 = make_float2(hs * u.x + hc * v.x, hs * u.y + hc * v.y);
    }
    // 5) CNOT c=6,t=7: swap s10<->s11
    { float2 t = s10; s10 = s11; s11 = t; }
    // 6) RY(w23) on q7
    {
        float hs, hc; sincosf(0.5f * w23, &hs, &hc);
        float2 u = s00, v = s01;
        s00 = make_float2(hc * u.x - hs * v.x, hc * u.y - hs * v.y);
        s01 = make_float2(hs * u.x + hc * v.x, hs * u.y + hc * v.y);
        u = s10; v = s11;
        s10 = make_float2(hc * u.x - hs * v.x, hc * u.y - hs * v.y);
        s11 = make_float2(hs * u.x + hc * v.x, hs * u.y + hc * v.y);
    }

    // <Z_7> = P(b7=0) - P(b7=1)
    float z = (s00.x * s00.x + s00.y * s00.y) + (s10.x * s10.x + s10.y * s10.y)
            - (s01.x * s01.x + s01.y * s01.y) - (s11.x * s11.x + s11.y * s11.y);
    out[i] = z;
}

// ---------------------------------------------------------------------------
// Kernel B: QLSTM. Closed form for qgate:
//   c_i = cos(v_i + theta_i)
//   qgate = [c1*c2*c3, c0*c1, c0*c1*c2, c0*c1*c2*c3]
// One block, 64 threads: thread = (batch b = t>>2, gate g = t&3).
// Sequential over S=128 steps; h,c in shared memory.
// ---------------------------------------------------------------------------
__global__ void lstm_kernel(const float* __restrict__ qcnn,   // d_out[0:2048], (B,S)
                            const float* __restrict__ thf, const float* __restrict__ thi,
                            const float* __restrict__ thg, const float* __restrict__ tho,
                            const float* __restrict__ Wf, const float* __restrict__ bf,
                            const float* __restrict__ Wi, const float* __restrict__ bi,
                            const float* __restrict__ Wg, const float* __restrict__ bg,
                            const float* __restrict__ Wo, const float* __restrict__ bo,
                            const float* __restrict__ Wh, const float* __restrict__ bh,
                            float* __restrict__ out_logits) {
    __shared__ float h[16][4];
    __shared__ float c[16][4];
    __shared__ float gv[4][16][4];   // [gate][batch][component]

    int t = threadIdx.x;             // 0..63
    int b = t >> 2;
    int g = t & 3;

    h[b][g] = 0.0f;
    c[b][g] = 0.0f;

    const float* Wsel = (g == 0) ? Wf : (g == 1) ? Wi : (g == 2) ? Wg : Wo;
    const float* bsel = (g == 0) ? bf : (g == 1) ? bi : (g == 2) ? bg : bo;
    const float* tsel = (g == 0) ? thf : (g == 1) ? thi : (g == 2) ? thg : tho;

    float W[20], bb[4], th[4];
#pragma unroll
    for (int k = 0; k < 20; k++) W[k] = Wsel[k];
#pragma unroll
    for (int k = 0; k < 4; k++) { bb[k] = bsel[k]; th[k] = tsel[k]; }

    __syncthreads();

    for (int s = 0; s < 128; s++) {
        float x0 = qcnn[b * 128 + s];
        float h0 = h[b][0], h1 = h[b][1], h2 = h[b][2], h3 = h[b][3];

        float ci[4];
#pragma unroll
        for (int r = 0; r < 4; r++) {
            float v = bb[r]
                    + W[r * 5 + 0] * x0
                    + W[r * 5 + 1] * h0
                    + W[r * 5 + 2] * h1
                    + W[r * 5 + 3] * h2
                    + W[r * 5 + 4] * h3;
            ci[r] = cosf(v + th[r]);
        }
        float z1 = ci[0] * ci[1];
        float z2 = z1 * ci[2];
        float z3 = z2 * ci[3];
        float z0 = ci[1] * ci[2] * ci[3];
        float z[4] = { z0, z1, z2, z3 };

        if (g == 2) {
#pragma unroll
            for (int j = 0; j < 4; j++) gv[g][b][j] = tanhf(z[j]);
        } else {
#pragma unroll
            for (int j = 0; j < 4; j++) gv[g][b][j] = 1.0f / (1.0f + expf(-z[j]));
        }
        __syncthreads();

        // update component j = g of batch b
        {
            int j = g;
            float fv = gv[0][b][j];
            float iv = gv[1][b][j];
            float gg = gv[2][b][j];
            float ov = gv[3][b][j];
            float cn = fv * c[b][j] + iv * gg;
            c[b][j] = cn;
            h[b][j] = ov * tanhf(cn);
        }
        __syncthreads();
    }

    if (g == 0) {
        float l = bh[0];
#pragma unroll
        for (int j = 0; j < 4; j++) l += Wh[j] * h[b][j];
        out_logits[b] = l;
    }
}

// ---------------------------------------------------------------------------
// Launch
// ---------------------------------------------------------------------------
extern "C" void kernel_launch(void* const* d_in, const int* in_sizes, int n_in,
                              void* d_out, int out_size) {
    const float* x   = (const float*)d_in[0];   // (16,128,8)
    const float* qw  = (const float*)d_in[1];   // (42,)
    const float* thf = (const float*)d_in[2];
    const float* thi = (const float*)d_in[3];
    const float* thg = (const float*)d_in[4];
    const float* tho = (const float*)d_in[5];
    const float* Wf  = (const float*)d_in[6];
    const float* bf  = (const float*)d_in[7];
    const float* Wi  = (const float*)d_in[8];
    const float* bi  = (const float*)d_in[9];
    const float* Wg  = (const float*)d_in[10];
    const float* bg  = (const float*)d_in[11];
    const float* Wo  = (const float*)d_in[12];
    const float* bo  = (const float*)d_in[13];
    const float* Wh  = (const float*)d_in[14];
    const float* bh  = (const float*)d_in[15];

    float* out = (float*)d_out;   // [0:2048] qcnn_out, [2048:2064] logits

    qcnn_kernel<<<8, 256>>>(x, qw, out);
    lstm_kernel<<<1, 64>>>(out, thf, thi, thg, tho,
                           Wf, bf, Wi, bi, Wg, bg, Wo, bo, Wh, bh,
                           out + 2048);
}

// round 3
// speedup vs baseline: 2.8712x; 2.8712x over previous
#include <cuda_runtime.h>
#include <math.h>

// ---------------------------------------------------------------------------
// Complex helpers (float2 = {re, im})
// ---------------------------------------------------------------------------
__device__ __forceinline__ float2 cmul(float2 a, float2 b) {
    return make_float2(a.x * b.x - a.y * b.y, a.x * b.y + a.y * b.x);
}

__device__ __forceinline__ float fex2(float x) {
    float r; asm("ex2.approx.f32 %0, %1;" : "=f"(r) : "f"(x)); return r;
}
__device__ __forceinline__ float frcp(float x) {
    float r; asm("rcp.approx.f32 %0, %1;" : "=f"(r) : "f"(x)); return r;
}

// ---------------------------------------------------------------------------
// Kernel A: QCNN. The 8-qubit circuit factorizes over pairs (0,1)(2,3)(4,5)(6,7);
// Z_7 depends only on the (6,7) subsystem -> 4-amplitude simulation.
// Relevant params: w[9:12] (conv on (6,7)), w[21:24] (pool on (6,7)).
// ---------------------------------------------------------------------------
__global__ void qcnn_kernel(const float* __restrict__ x,
                            const float* __restrict__ w,
                            float* __restrict__ out) {
    int i = blockIdx.x * blockDim.x + threadIdx.x;
    if (i >= 2048) return;

    float2 q6a0, q6a1, q7a0, q7a1;
    {
        float ph = 2.0f * x[i * 8 + 6];
        float sp, cp; sincosf(ph, &sp, &cp);
        q6a0 = make_float2(0.5f * (1.0f + cp), 0.5f * sp);
        float2 t = make_float2(0.5f * (1.0f - cp), -0.5f * sp);
        q6a1 = make_float2(cp * t.x - sp * t.y, cp * t.y + sp * t.x);
    }
    {
        float ph = 2.0f * x[i * 8 + 7];
        float sp, cp; sincosf(ph, &sp, &cp);
        q7a0 = make_float2(0.5f * (1.0f + cp), 0.5f * sp);
        float2 t = make_float2(0.5f * (1.0f - cp), -0.5f * sp);
        q7a1 = make_float2(cp * t.x - sp * t.y, cp * t.y + sp * t.x);
    }

    float2 s00 = cmul(q6a0, q7a0);
    float2 s01 = cmul(q6a0, q7a1);
    float2 s10 = cmul(q6a1, q7a0);
    float2 s11 = cmul(q6a1, q7a1);

    const float R = 0.70710678118654752f;
    const float2 ePp = make_float2(R,  R);   // e^{+i pi/4}
    const float2 ePm = make_float2(R, -R);   // e^{-i pi/4}

    float w9 = w[9], w10 = w[10], w11 = w[11];
    float w21 = w[21], w22 = w[22], w23 = w[23];

    // ---- conv_block(w[9:12], q1=6, q2=7) ----
    s00 = cmul(s00, ePp); s10 = cmul(s10, ePp);
    s01 = cmul(s01, ePm); s11 = cmul(s11, ePm);
    { float2 t = s01; s01 = s11; s11 = t; }          // CX(7,6)
    {
        float hs, hc; sincosf(0.5f * w9, &hs, &hc);  // RZ(w9) q6
        float2 em = make_float2(hc, -hs), ep = make_float2(hc, hs);
        s00 = cmul(s00, em); s01 = cmul(s01, em);
        s10 = cmul(s10, ep); s11 = cmul(s11, ep);
    }
    {
        float hs, hc; sincosf(0.5f * w10, &hs, &hc); // RY(w10) q7
        float2 u = s00, v = s01;
        s00 = make_float2(hc * u.x - hs * v.x, hc * u.y - hs * v.y);
        s01 = make_float2(hs * u.x + hc * v.x, hs * u.y + hc * v.y);
        u = s10; v = s11;
        s10 = make_float2(hc * u.x - hs * v.x, hc * u.y - hs * v.y);
        s11 = make_float2(hs * u.x + hc * v.x, hs * u.y + hc * v.y);
    }
    { float2 t = s10; s10 = s11; s11 = t; }          // CX(6,7)
    {
        float hs, hc; sincosf(0.5f * w11, &hs, &hc); // RY(w11) q7
        float2 u = s00, v = s01;
        s00 = make_float2(hc * u.x - hs * v.x, hc * u.y - hs * v.y);
        s01 = make_float2(hs * u.x + hc * v.x, hs * u.y + hc * v.y);
        u = s10; v = s11;
        s10 = make_float2(hc * u.x - hs * v.x, hc * u.y - hs * v.y);
        s11 = make_float2(hs * u.x + hc * v.x, hs * u.y + hc * v.y);
    }
    { float2 t = s01; s01 = s11; s11 = t; }          // CX(7,6)
    s00 = cmul(s00, ePm); s01 = cmul(s01, ePm);      // RZ(pi/2) q6
    s10 = cmul(s10, ePp); s11 = cmul(s11, ePp);

    // ---- pool_block(w[21:24], src=6, sink=7) ----
    s00 = cmul(s00, ePp); s10 = cmul(s10, ePp);
    s01 = cmul(s01, ePm); s11 = cmul(s11, ePm);
    { float2 t = s01; s01 = s11; s11 = t; }          // CX(7,6)
    {
        float hs, hc; sincosf(0.5f * w21, &hs, &hc); // RZ(w21) q6
        float2 em = make_float2(hc, -hs), ep = make_float2(hc, hs);
        s00 = cmul(s00, em); s01 = cmul(s01, em);
        s10 = cmul(s10, ep); s11 = cmul(s11, ep);
    }
    {
        float hs, hc; sincosf(0.5f * w22, &hs, &hc); // RY(w22) q7
        float2 u = s00, v = s01;
        s00 = make_float2(hc * u.x - hs * v.x, hc * u.y - hs * v.y);
        s01 = make_float2(hs * u.x + hc * v.x, hs * u.y + hc * v.y);
        u = s10; v = s11;
        s10 = make_float2(hc * u.x - hs * v.x, hc * u.y - hs * v.y);
        s11 = make_float2(hs * u.x + hc * v.x, hs * u.y + hc * v.y);
    }
    { float2 t = s10; s10 = s11; s11 = t; }          // CX(6,7)
    {
        float hs, hc; sincosf(0.5f * w23, &hs, &hc); // RY(w23) q7
        float2 u = s00, v = s01;
        s00 = make_float2(hc * u.x - hs * v.x, hc * u.y - hs * v.y);
        s01 = make_float2(hs * u.x + hc * v.x, hs * u.y + hc * v.y);
        u = s10; v = s11;
        s10 = make_float2(hc * u.x - hs * v.x, hc * u.y - hs * v.y);
        s11 = make_float2(hs * u.x + hc * v.x, hs * u.y + hc * v.y);
    }

    float z = (s00.x * s00.x + s00.y * s00.y) + (s10.x * s10.x + s10.y * s10.y)
            - (s01.x * s01.x + s01.y * s01.y) - (s11.x * s11.x + s11.y * s11.y);
    out[i] = z;
}

// ---------------------------------------------------------------------------
// Kernel B: QLSTM, warp-synchronous, zero barriers, zero shared memory.
// Closed form: c_i = cos(v_i + theta_i); qgate = [c1c2c3, c0c1, c0c1c2, c0c1c2c3].
// 64 threads (2 warps). thread t: batch b = t>>2 (lane group of 4), gate g = t&3.
// Gate<->component exchange via a 4-shuffle butterfly 4x4 transpose; h via
// a 4-shuffle broadcast. Activations: sig(x)=rcp(1+ex2(-x*log2e)),
// tanh(x)=2*rcp(1+ex2(-2x*log2e))-1.
// ---------------------------------------------------------------------------
__global__ void lstm_kernel(const float* __restrict__ qcnn,   // (B=16, S=128)
                            const float* __restrict__ thf, const float* __restrict__ thi,
                            const float* __restrict__ thg, const float* __restrict__ tho,
                            const float* __restrict__ Wf, const float* __restrict__ bf,
                            const float* __restrict__ Wi, const float* __restrict__ bi,
                            const float* __restrict__ Wg, const float* __restrict__ bg,
                            const float* __restrict__ Wo, const float* __restrict__ bo,
                            const float* __restrict__ Wh, const float* __restrict__ bh,
                            float* __restrict__ out_logits) {
    const unsigned FULL = 0xffffffffu;
    const float L2E = 1.4426950408889634f;

    int t = threadIdx.x;             // 0..63
    int b = t >> 2;
    int g = t & 3;
    int lane = t & 31;

    const float* Wsel = (g == 0) ? Wf : (g == 1) ? Wi : (g == 2) ? Wg : Wo;
    const float* bsel = (g == 0) ? bf : (g == 1) ? bi : (g == 2) ? bg : bo;
    const float* tsel = (g == 0) ? thf : (g == 1) ? thi : (g == 2) ? thg : tho;

    float W[20], bb[4];
#pragma unroll
    for (int k = 0; k < 20; k++) W[k] = Wsel[k];
#pragma unroll
    for (int k = 0; k < 4; k++) bb[k] = bsel[k] + tsel[k];  // fold theta into bias

    float h0 = 0.f, h1 = 0.f, h2 = 0.f, h3 = 0.f;
    float cm = 0.f;                                   // c[b][g]

    const float* xp = qcnn + b * 128;
    float x0 = xp[0];

    for (int s = 0; s < 128; s++) {
        // prefetch next x (independent of recurrence)
        float xn = xp[(s < 127) ? (s + 1) : 127];

        // v_r = bb[r] + W[r] . [x0, h0..h3], r = 0..3 (my gate's 4 rows)
        float ci0, ci1, ci2, ci3;
        {
#pragma unroll
            for (int r = 0; r < 4; r++) {
                float a  = fmaf(W[r * 5 + 0], x0, bb[r]);
                float u  = W[r * 5 + 2] * h1;
                float p  = fmaf(W[r * 5 + 1], h0, a);
                float q  = fmaf(W[r * 5 + 3], h2, u);
                float v  = fmaf(W[r * 5 + 4], h3, p) + q;
                float cc = __cosf(v);
                if (r == 0) ci0 = cc; else if (r == 1) ci1 = cc;
                else if (r == 2) ci2 = cc; else ci3 = cc;
            }
        }

        // qgate outputs for my gate
        float c23 = ci2 * ci3;
        float z1  = ci0 * ci1;
        float z0  = ci1 * c23;
        float z2  = z1 * ci2;
        float z3  = z1 * c23;

        // 4x4 transpose across the 4-lane group: after, a[k] = gate k's z[g]
        float a0 = z0, a1 = z1, a2 = z2, a3 = z3;
        {
            // round 1: xor 1, pairs (a0,a1) and (a2,a3)
            float s01 = (g & 1) ? a0 : a1;
            float r01 = __shfl_xor_sync(FULL, s01, 1);
            if (g & 1) a0 = r01; else a1 = r01;
            float s23 = (g & 1) ? a2 : a3;
            float r23 = __shfl_xor_sync(FULL, s23, 1);
            if (g & 1) a2 = r23; else a3 = r23;
            // round 2: xor 2, pairs (a0,a2) and (a1,a3)
            float s02 = (g & 2) ? a0 : a2;
            float r02 = __shfl_xor_sync(FULL, s02, 2);
            if (g & 2) a0 = r02; else a2 = r02;
            float s13 = (g & 2) ? a1 : a3;
            float r13 = __shfl_xor_sync(FULL, s13, 2);
            if (g & 2) a1 = r13; else a3 = r13;
        }

        // fixed activation pattern: f=sig(a0), i=sig(a1), g=tanh(a2), o=sig(a3)
        float fv = frcp(1.0f + fex2(-L2E * a0));
        float iv = frcp(1.0f + fex2(-L2E * a1));
        float gv = fmaf(2.0f, frcp(1.0f + fex2(-2.0f * L2E * a2)), -1.0f);
        float ov = frcp(1.0f + fex2(-L2E * a3));

        // update component j = g
        float cn = fmaf(fv, cm, iv * gv);
        cm = cn;
        float tc = fmaf(2.0f, frcp(1.0f + fex2(-2.0f * L2E * cn)), -1.0f);
        float hm = ov * tc;

        // broadcast h within the 4-lane group
        int base = lane & ~3;
        h0 = __shfl_sync(FULL, hm, base + 0);
        h1 = __shfl_sync(FULL, hm, base + 1);
        h2 = __shfl_sync(FULL, hm, base + 2);
        h3 = __shfl_sync(FULL, hm, base + 3);

        x0 = xn;
    }

    if (g == 0) {
        float l = bh[0];
        l = fmaf(Wh[0], h0, l);
        l = fmaf(Wh[1], h1, l);
        l = fmaf(Wh[2], h2, l);
        l = fmaf(Wh[3], h3, l);
        out_logits[b] = l;
    }
}

// ---------------------------------------------------------------------------
// Launch
// ---------------------------------------------------------------------------
extern "C" void kernel_launch(void* const* d_in, const int* in_sizes, int n_in,
                              void* d_out, int out_size) {
    const float* x   = (const float*)d_in[0];   // (16,128,8)
    const float* qw  = (const float*)d_in[1];   // (42,)
    const float* thf = (const float*)d_in[2];
    const float* thi = (const float*)d_in[3];
    const float* thg = (const float*)d_in[4];
    const float* tho = (const float*)d_in[5];
    const float* Wf  = (const float*)d_in[6];
    const float* bf  = (const float*)d_in[7];
    const float* Wi  = (const float*)d_in[8];
    const float* bi  = (const float*)d_in[9];
    const float* Wg  = (const float*)d_in[10];
    const float* bg  = (const float*)d_in[11];
    const float* Wo  = (const float*)d_in[12];
    const float* bo  = (const float*)d_in[13];
    const float* Wh  = (const float*)d_in[14];
    const float* bh  = (const float*)d_in[15];

    float* out = (float*)d_out;   // [0:2048] qcnn_out, [2048:2064] logits

    qcnn_kernel<<<8, 256>>>(x, qw, out);
    lstm_kernel<<<1, 64>>>(out, thf, thi, thg, tho,
                           Wf, bf, Wi, bi, Wg, bg, Wo, bo, Wh, bh,
                           out + 2048);
}